// round 8
// baseline (speedup 1.0000x reference)
#include <cuda_runtime.h>
#include <cstdint>

typedef unsigned long long ull;

// Problem constants
#define DDIM 4096
#define NEXP 64
#define NTOK 16384          // B*S
#define BM   128
#define BK   32
#define NSTAGE (DDIM / BK)  // 128
#define NCTA (NTOK / BM)    // 128

// Output layout (tuple flattened to float32 in reference order)
#define IDX_OFF   0
#define SC_OFF    32768
#define PB_OFF    65536
#define Z_OFF     1114112
#define IMP_OFF   1114113
#define LOAD_OFF  1114177

// Per-CTA partial stats: [0..63] importance, [64..127] counts, [128] z^2
__device__ float g_part[NCTA][129];
__device__ unsigned int g_ctr = 0;   // self-resetting via atomicInc wrap

// ---------- PTX helpers ----------
__device__ __forceinline__ ull ffma2(ull a, ull b, ull c) {
    ull d;
    asm("fma.rn.f32x2 %0, %1, %2, %3;" : "=l"(d) : "l"(a), "l"(b), "l"(c));
    return d;
}
__device__ __forceinline__ void cp16(uint32_t dst, const void* src) {
    asm volatile("cp.async.cg.shared.global [%0], [%1], 16;" :: "r"(dst), "l"(src));
}
__device__ __forceinline__ void cp_commit() {
    asm volatile("cp.async.commit_group;" ::: "memory");
}
template <int N> __device__ __forceinline__ void cp_wait() {
    asm volatile("cp.async.wait_group %0;" :: "n"(N) : "memory");
}

// ---------- single fused kernel ----------
// grid = 128 CTAs (one per 128-token tile), block = 512 threads (4 warps/SMSP).
// Thread tile: 4 rows x 4 experts (32 acc regs). Mapping: tm=tid>>4 (32 row
// groups), tn=tid&15 (16 expert groups) -> x loads broadcast (2 addrs/warp),
// w loads 16 addrs/warp, conflict-free via quad swizzle.
extern "C" __global__ void __launch_bounds__(512, 1)
router_kernel(const float* __restrict__ x, const float* __restrict__ W,
              float* __restrict__ out) {
    // 12288 floats = 48KB static smem.
    //   xs0 [0..4095], ws0 [4096..6143], xs1 [6144..10239], ws1 [10240..12287]
    // After mainloop: ls (128x65 = 8320) at sm[0..8319], stats at sm[8320..8448]
    __shared__ float sm[12288];
    float* xs[2] = { sm,        sm + 6144 };
    float* ws[2] = { sm + 4096, sm + 10240 };
    uint32_t xs_a[2], ws_a[2];
    xs_a[0] = (uint32_t)__cvta_generic_to_shared(xs[0]);
    xs_a[1] = (uint32_t)__cvta_generic_to_shared(xs[1]);
    ws_a[0] = (uint32_t)__cvta_generic_to_shared(ws[0]);
    ws_a[1] = (uint32_t)__cvta_generic_to_shared(ws[1]);

    const int tid = threadIdx.x;
    const int tm = tid >> 4;      // row group (32):    rows tm + 32*i, i<4
    const int tn = tid & 15;      // expert group (16): experts tn + 16*j, j<4
    const int rowbase = blockIdx.x * BM;

    // ---- stage loader: quad (16B) swizzle — quad q of row r stored at q^(r&7) ----
    auto load_stage = [&](int s, int b) {
        const float* xg = x + (size_t)rowbase * DDIM + s * BK;
        #pragma unroll
        for (int i = 0; i < 2; i++) {
            int c = tid + 512 * i;          // 1024 quads: 128 rows x 8 quads
            int r = c >> 3;
            int q = c & 7;
            uint32_t dst = xs_a[b] + (uint32_t)((r * 32 + ((q ^ (r & 7)) << 2)) * 4);
            cp16(dst, xg + (size_t)r * DDIM + (q << 2));
        }
        {
            const float* wg = W + s * BK;
            int r = tid >> 3;               // 512 quads: 64 rows x 8 quads
            int q = tid & 7;
            uint32_t dst = ws_a[b] + (uint32_t)((r * 32 + ((q ^ (r & 7)) << 2)) * 4);
            cp16(dst, wg + (size_t)r * DDIM + (q << 2));
        }
        cp_commit();
    };

    ull acc[4][4];
    #pragma unroll
    for (int i = 0; i < 4; i++)
        #pragma unroll
        for (int j = 0; j < 4; j++) acc[i][j] = 0ull;

    load_stage(0, 0);

    const int xo = tm & 7;   // x de-swizzle (rows tm+32i keep r&7 == tm&7)
    const int wo = tn & 7;   // w de-swizzle (rows tn+16j keep r&7 == tn&7)

    #pragma unroll 1
    for (int s = 0; s < NSTAGE; s++) {
        if (s + 1 < NSTAGE) {
            load_stage(s + 1, (s + 1) & 1);
            cp_wait<1>();
        } else {
            cp_wait<0>();
        }
        __syncthreads();

        const float* Xr = xs[s & 1] + tm * 32;
        const float* Wr = ws[s & 1] + tn * 32;

        #pragma unroll 2
        for (int kq = 0; kq < 8; kq++) {    // 8 quads = 16 k-pairs per stage
            const ulonglong2* xp = (const ulonglong2*)(Xr + ((kq ^ xo) << 2));
            const ulonglong2* wp = (const ulonglong2*)(Wr + ((kq ^ wo) << 2));
            ulonglong2 xv[4], wv[4];
            #pragma unroll
            for (int i = 0; i < 4; i++) xv[i] = xp[i * 256];   // +32 rows (1024 floats)
            #pragma unroll
            for (int j = 0; j < 4; j++) wv[j] = wp[j * 128];   // +16 rows (512 floats)
            #pragma unroll
            for (int i = 0; i < 4; i++)
                #pragma unroll
                for (int j = 0; j < 4; j++)
                    acc[i][j] = ffma2(xv[i].x, wv[j].x, acc[i][j]);
            #pragma unroll
            for (int i = 0; i < 4; i++)
                #pragma unroll
                for (int j = 0; j < 4; j++)
                    acc[i][j] = ffma2(xv[i].y, wv[j].y, acc[i][j]);
        }
        __syncthreads();
    }

    // ---- epilogue: logits -> smem (stride 65 to kill STS bank conflicts) ----
    float* ls = sm;                 // [128][65]
    float* st = sm + 8320;          // [129] CTA stats
    #pragma unroll
    for (int i = 0; i < 4; i++)
        #pragma unroll
        for (int j = 0; j < 4; j++) {
            float lo = __uint_as_float((uint32_t)(acc[i][j] & 0xffffffffull));
            float hi = __uint_as_float((uint32_t)(acc[i][j] >> 32));
            ls[(tm + 32 * i) * 65 + (tn + 16 * j)] = lo + hi;
        }
    if (tid < 129) st[tid] = 0.0f;
    __syncthreads();

    // ---- router: 16 warps, 8 rows per warp ----
    const int warp = tid >> 5;
    const int lane = tid & 31;
    const float NEG_INF = __int_as_float(0xff800000u);
    float imp0 = 0.f, imp1 = 0.f, cnt0 = 0.f, cnt1 = 0.f, z2 = 0.f;
    float* probs_out = out + PB_OFF;

    #pragma unroll 2
    for (int it = 0; it < 8; it++) {
        const int rl = warp * 8 + it;
        const int row = rowbase + rl;
        const float va = ls[rl * 65 + lane];
        const float vb = ls[rl * 65 + lane + 32];

        // top-1 (ties -> lower index)
        float bv; int bi;
        if (va >= vb) { bv = va; bi = lane; } else { bv = vb; bi = lane + 32; }
        #pragma unroll
        for (int off = 16; off; off >>= 1) {
            float ov = __shfl_xor_sync(0xffffffffu, bv, off);
            int   oi = __shfl_xor_sync(0xffffffffu, bi, off);
            if (ov > bv || (ov == bv && oi < bi)) { bv = ov; bi = oi; }
        }
        // top-2 (exclude bi)
        float va2 = (lane == bi)      ? NEG_INF : va;
        float vb2 = (lane + 32 == bi) ? NEG_INF : vb;
        float sv; int si;
        if (va2 >= vb2) { sv = va2; si = lane; } else { sv = vb2; si = lane + 32; }
        #pragma unroll
        for (int off = 16; off; off >>= 1) {
            float ov = __shfl_xor_sync(0xffffffffu, sv, off);
            int   oi = __shfl_xor_sync(0xffffffffu, si, off);
            if (ov > sv || (ov == sv && oi < si)) { sv = ov; si = oi; }
        }

        // full softmax (max-shifted)
        const float ea = __expf(va - bv);
        const float eb = __expf(vb - bv);
        float ssum = ea + eb;
        #pragma unroll
        for (int off = 16; off; off >>= 1)
            ssum += __shfl_xor_sync(0xffffffffu, ssum, off);
        const float inv = 1.0f / ssum;
        const float pa = ea * inv, pb = eb * inv;

        probs_out[(size_t)row * 64 + lane]      = pa;
        probs_out[(size_t)row * 64 + lane + 32] = pb;

        imp0 += pa; imp1 += pb;
        cnt0 += (bi == lane      ? 1.f : 0.f) + (si == lane      ? 1.f : 0.f);
        cnt1 += (bi == lane + 32 ? 1.f : 0.f) + (si == lane + 32 ? 1.f : 0.f);

        if (lane == 0) {
            const float z = bv + __logf(ssum);
            z2 += z * z;
            out[IDX_OFF + row * 2]     = (float)bi;
            out[IDX_OFF + row * 2 + 1] = (float)si;
            const float e2 = __expf(sv - bv);
            const float dn = 1.0f / (1.0f + e2);
            out[SC_OFF + row * 2]     = dn;
            out[SC_OFF + row * 2 + 1] = e2 * dn;
        }
    }

    // ---- CTA-level stats reduce in smem, then one row of g_part ----
    atomicAdd(&st[lane],      imp0);
    atomicAdd(&st[lane + 32], imp1);
    atomicAdd(&st[64 + lane], cnt0);
    atomicAdd(&st[96 + lane], cnt1);
    if (lane == 0) atomicAdd(&st[128], z2);
    __syncthreads();

    if (tid < 129) g_part[blockIdx.x][tid] = st[tid];

    // ---- last-CTA finalize (self-resetting counter) ----
    __shared__ unsigned int s_last;
    __threadfence();
    __syncthreads();
    if (tid == 0) {
        unsigned int old = atomicInc(&g_ctr, NCTA - 1);
        s_last = (old == NCTA - 1) ? 1u : 0u;
    }
    __syncthreads();
    if (s_last && tid < 129) {
        __threadfence();
        float ssum = 0.f;
        #pragma unroll 1
        for (int c = 0; c < NCTA; c++) ssum += g_part[c][tid];
        if (tid < 64)       out[IMP_OFF + tid]         = ssum * (1.0f / 16384.0f);
        else if (tid < 128) out[LOAD_OFF + (tid - 64)] = ssum * (1.0f / 32768.0f);
        else                out[Z_OFF]                 = ssum * (1.0f / 16384.0f);
    }
}

extern "C" void kernel_launch(void* const* d_in, const int* in_sizes, int n_in,
                              void* d_out, int out_size) {
    const float* x = (const float*)d_in[0];   // [4,4096,4096] f32
    const float* W = (const float*)d_in[1];   // [64,4096] f32
    float* out = (float*)d_out;
    (void)in_sizes; (void)n_in; (void)out_size;
    router_kernel<<<NCTA, 512>>>(x, W, out);
}

// round 9
// speedup vs baseline: 1.4424x; 1.4424x over previous
#include <cuda_runtime.h>
#include <cstdint>

// Problem constants
#define DDIM 4096
#define NEXP 64
#define NTOK 16384          // B*S
#define BM   128
#define KC   32             // K per stage
#define NSTAGE (DDIM / KC)  // 128
#define NCTA (NTOK / BM)    // 128
#define S36  36             // smem row stride (36 mod 32 = 4 -> conflict-free frags)

// Output layout (tuple flattened to float32 in reference order)
#define IDX_OFF   0
#define SC_OFF    32768
#define PB_OFF    65536
#define Z_OFF     1114112
#define IMP_OFF   1114113
#define LOAD_OFF  1114177

// Dynamic smem (float offsets): xh[2]@0/4608, xl[2]@9216/13824,
// wh[2]@18432/20736, wl[2]@23040/25344. Total 27648 floats = 108KB.
// After mainloop: ls[128][65] @0, st[129] @8320 (reuse).
#define XH(b) ((b) * 4608)
#define XL(b) (9216 + (b) * 4608)
#define WH(b) (18432 + (b) * 2304)
#define WL(b) (23040 + (b) * 2304)
#define DSM_BYTES (27648 * 4)

// Per-CTA partial stats: [0..63] importance, [64..127] counts, [128] z^2
__device__ float g_part[NCTA][129];
__device__ unsigned int g_ctr = 0;   // self-resetting via atomicInc wrap

// ---------- helpers ----------
__device__ __forceinline__ void tf32pair(float v, uint32_t& h, uint32_t& l) {
    asm("cvt.rna.tf32.f32 %0, %1;" : "=r"(h) : "f"(v));
    float r = v - __uint_as_float(h);
    asm("cvt.rna.tf32.f32 %0, %1;" : "=r"(l) : "f"(r));
}
__device__ __forceinline__ void mma8(float* d,
                                     uint32_t a0, uint32_t a1, uint32_t a2, uint32_t a3,
                                     uint32_t b0, uint32_t b1) {
    asm volatile(
        "mma.sync.aligned.m16n8k8.row.col.f32.tf32.tf32.f32 "
        "{%0,%1,%2,%3},{%4,%5,%6,%7},{%8,%9},{%0,%1,%2,%3};"
        : "+f"(d[0]), "+f"(d[1]), "+f"(d[2]), "+f"(d[3])
        : "r"(a0), "r"(a1), "r"(a2), "r"(a3), "r"(b0), "r"(b1));
}

// ---------- single fused kernel ----------
// grid = 128 CTAs (one per 128-token tile), block = 256 threads (8 warps).
// Each warp computes 16 rows x 64 experts via m16n8k8 tf32 mma, 4-product
// fp32 emulation (hh + hl + lh + ll).
extern "C" __global__ void __launch_bounds__(256, 1)
router_kernel(const float* __restrict__ x, const float* __restrict__ W,
              float* __restrict__ out) {
    extern __shared__ __align__(16) float dsm[];

    const int tid  = threadIdx.x;
    const int warp = tid >> 5;
    const int lane = tid & 31;
    const int g = lane >> 2;      // group row
    const int t = lane & 3;       // thread-in-group
    const int rowbase = blockIdx.x * BM;
    const float* xg0 = x + (size_t)rowbase * DDIM;

    // ---- register-prefetch double-buffered loader ----
    // x: 1024 quads/stage -> 4 per thread; w: 512 quads -> 2 per thread.
    float4 xr[4], wr[2];
    #pragma unroll
    for (int i = 0; i < 4; i++) {
        int c = tid + 256 * i, r = c >> 3, q = c & 7;
        xr[i] = *(const float4*)(xg0 + (size_t)r * DDIM + (q << 2));
    }
    #pragma unroll
    for (int i = 0; i < 2; i++) {
        int c = tid + 256 * i, r = c >> 3, q = c & 7;
        wr[i] = *(const float4*)(W + (size_t)r * DDIM + (q << 2));
    }

    float acc[8][4];
    #pragma unroll
    for (int nt = 0; nt < 8; nt++)
        #pragma unroll
        for (int e = 0; e < 4; e++) acc[nt][e] = 0.0f;

    const int wrow = warp * 16;

    #pragma unroll 1
    for (int s = 0; s < NSTAGE; s++) {
        const int b = s & 1;

        // prefetch next stage
        float4 xn[4], wn[2];
        if (s + 1 < NSTAGE) {
            const float* xg = xg0 + (s + 1) * KC;
            const float* wg = W + (s + 1) * KC;
            #pragma unroll
            for (int i = 0; i < 4; i++) {
                int c = tid + 256 * i, r = c >> 3, q = c & 7;
                xn[i] = *(const float4*)(xg + (size_t)r * DDIM + (q << 2));
            }
            #pragma unroll
            for (int i = 0; i < 2; i++) {
                int c = tid + 256 * i, r = c >> 3, q = c & 7;
                wn[i] = *(const float4*)(wg + (size_t)r * DDIM + (q << 2));
            }
        }

        // convert current stage fp32 -> (tf32 hi, tf32 lo), store to smem
        #pragma unroll
        for (int i = 0; i < 4; i++) {
            int c = tid + 256 * i, r = c >> 3, q = c & 7;
            uint4 h, l;
            tf32pair(xr[i].x, h.x, l.x);
            tf32pair(xr[i].y, h.y, l.y);
            tf32pair(xr[i].z, h.z, l.z);
            tf32pair(xr[i].w, h.w, l.w);
            int off = r * S36 + (q << 2);
            *(uint4*)(dsm + XH(b) + off) = h;
            *(uint4*)(dsm + XL(b) + off) = l;
        }
        #pragma unroll
        for (int i = 0; i < 2; i++) {
            int c = tid + 256 * i, r = c >> 3, q = c & 7;
            uint4 h, l;
            tf32pair(wr[i].x, h.x, l.x);
            tf32pair(wr[i].y, h.y, l.y);
            tf32pair(wr[i].z, h.z, l.z);
            tf32pair(wr[i].w, h.w, l.w);
            int off = r * S36 + (q << 2);
            *(uint4*)(dsm + WH(b) + off) = h;
            *(uint4*)(dsm + WL(b) + off) = l;
        }
        __syncthreads();

        // ---- MMA phase: 4 k8-steps, 8 n-tiles, 4 products each ----
        const uint32_t* xh = (const uint32_t*)(dsm + XH(b)) + (wrow + g) * S36 + t;
        const uint32_t* xl = (const uint32_t*)(dsm + XL(b)) + (wrow + g) * S36 + t;
        const uint32_t* wh = (const uint32_t*)(dsm + WH(b)) + g * S36 + t;
        const uint32_t* wl = (const uint32_t*)(dsm + WL(b)) + g * S36 + t;

        #pragma unroll
        for (int kq = 0; kq < 4; kq++) {
            const int k0 = kq * 8;
            // A frags: a0:(g,t) a1:(g+8,t) a2:(g,t+4) a3:(g+8,t+4)
            uint32_t ah0 = xh[k0],     ah1 = xh[8 * S36 + k0];
            uint32_t ah2 = xh[k0 + 4], ah3 = xh[8 * S36 + k0 + 4];
            uint32_t al0 = xl[k0],     al1 = xl[8 * S36 + k0];
            uint32_t al2 = xl[k0 + 4], al3 = xl[8 * S36 + k0 + 4];
            #pragma unroll
            for (int nt = 0; nt < 8; nt++) {
                // B frags: b0:(k=t, n=g) b1:(k=t+4, n=g); expert = nt*8+g
                const uint32_t* wph = wh + nt * 8 * S36;
                const uint32_t* wpl = wl + nt * 8 * S36;
                uint32_t bh0 = wph[k0], bh1 = wph[k0 + 4];
                uint32_t bl0 = wpl[k0], bl1 = wpl[k0 + 4];
                mma8(acc[nt], al0, al1, al2, al3, bl0, bl1);  // ll
                mma8(acc[nt], al0, al1, al2, al3, bh0, bh1);  // lh
                mma8(acc[nt], ah0, ah1, ah2, ah3, bl0, bl1);  // hl
                mma8(acc[nt], ah0, ah1, ah2, ah3, bh0, bh1);  // hh
            }
        }
        __syncthreads();

        #pragma unroll
        for (int i = 0; i < 4; i++) xr[i] = xn[i];
        #pragma unroll
        for (int i = 0; i < 2; i++) wr[i] = wn[i];
    }

    // ---- epilogue: logits -> smem ls[128][65] ----
    // C frags: c0:(g,2t) c1:(g,2t+1) c2:(g+8,2t) c3:(g+8,2t+1)
    float* ls = dsm;
    float* st = dsm + 8320;
    #pragma unroll
    for (int nt = 0; nt < 8; nt++) {
        const int c0 = nt * 8 + 2 * t;
        ls[(wrow + g) * 65 + c0]         = acc[nt][0];
        ls[(wrow + g) * 65 + c0 + 1]     = acc[nt][1];
        ls[(wrow + g + 8) * 65 + c0]     = acc[nt][2];
        ls[(wrow + g + 8) * 65 + c0 + 1] = acc[nt][3];
    }
    if (tid < 129) st[tid] = 0.0f;
    __syncthreads();

    // ---- router: 8 warps, 16 rows per warp (proven R6 code) ----
    const float NEG_INF = __int_as_float(0xff800000u);
    float imp0 = 0.f, imp1 = 0.f, cnt0 = 0.f, cnt1 = 0.f, z2 = 0.f;
    float* probs_out = out + PB_OFF;

    #pragma unroll 2
    for (int it = 0; it < 16; it++) {
        const int rl = warp * 16 + it;
        const int row = rowbase + rl;
        const float va = ls[rl * 65 + lane];
        const float vb = ls[rl * 65 + lane + 32];

        float bv; int bi;
        if (va >= vb) { bv = va; bi = lane; } else { bv = vb; bi = lane + 32; }
        #pragma unroll
        for (int off = 16; off; off >>= 1) {
            float ov = __shfl_xor_sync(0xffffffffu, bv, off);
            int   oi = __shfl_xor_sync(0xffffffffu, bi, off);
            if (ov > bv || (ov == bv && oi < bi)) { bv = ov; bi = oi; }
        }
        float va2 = (lane == bi)      ? NEG_INF : va;
        float vb2 = (lane + 32 == bi) ? NEG_INF : vb;
        float sv; int si;
        if (va2 >= vb2) { sv = va2; si = lane; } else { sv = vb2; si = lane + 32; }
        #pragma unroll
        for (int off = 16; off; off >>= 1) {
            float ov = __shfl_xor_sync(0xffffffffu, sv, off);
            int   oi = __shfl_xor_sync(0xffffffffu, si, off);
            if (ov > sv || (ov == sv && oi < si)) { sv = ov; si = oi; }
        }

        const float ea = __expf(va - bv);
        const float eb = __expf(vb - bv);
        float ssum = ea + eb;
        #pragma unroll
        for (int off = 16; off; off >>= 1)
            ssum += __shfl_xor_sync(0xffffffffu, ssum, off);
        const float inv = 1.0f / ssum;
        const float pa = ea * inv, pb = eb * inv;

        probs_out[(size_t)row * 64 + lane]      = pa;
        probs_out[(size_t)row * 64 + lane + 32] = pb;

        imp0 += pa; imp1 += pb;
        cnt0 += (bi == lane      ? 1.f : 0.f) + (si == lane      ? 1.f : 0.f);
        cnt1 += (bi == lane + 32 ? 1.f : 0.f) + (si == lane + 32 ? 1.f : 0.f);

        if (lane == 0) {
            const float z = bv + __logf(ssum);
            z2 += z * z;
            out[IDX_OFF + row * 2]     = (float)bi;
            out[IDX_OFF + row * 2 + 1] = (float)si;
            const float e2 = __expf(sv - bv);
            const float dn = 1.0f / (1.0f + e2);
            out[SC_OFF + row * 2]     = dn;
            out[SC_OFF + row * 2 + 1] = e2 * dn;
        }
    }

    // ---- CTA-level stats reduce in smem, then one row of g_part ----
    atomicAdd(&st[lane],      imp0);
    atomicAdd(&st[lane + 32], imp1);
    atomicAdd(&st[64 + lane], cnt0);
    atomicAdd(&st[96 + lane], cnt1);
    if (lane == 0) atomicAdd(&st[128], z2);
    __syncthreads();

    if (tid < 129) g_part[blockIdx.x][tid] = st[tid];

    // ---- last-CTA finalize (self-resetting counter) ----
    __shared__ unsigned int s_last;
    __threadfence();
    __syncthreads();
    if (tid == 0) {
        unsigned int old = atomicInc(&g_ctr, NCTA - 1);
        s_last = (old == NCTA - 1) ? 1u : 0u;
    }
    __syncthreads();
    if (s_last && tid < 129) {
        __threadfence();
        float ssum = 0.f;
        #pragma unroll 1
        for (int c = 0; c < NCTA; c++) ssum += g_part[c][tid];
        if (tid < 64)       out[IMP_OFF + tid]         = ssum * (1.0f / 16384.0f);
        else if (tid < 128) out[LOAD_OFF + (tid - 64)] = ssum * (1.0f / 32768.0f);
        else                out[Z_OFF]                 = ssum * (1.0f / 16384.0f);
    }
}

extern "C" void kernel_launch(void* const* d_in, const int* in_sizes, int n_in,
                              void* d_out, int out_size) {
    const float* x = (const float*)d_in[0];   // [4,4096,4096] f32
    const float* W = (const float*)d_in[1];   // [64,4096] f32
    float* out = (float*)d_out;
    (void)in_sizes; (void)n_in; (void)out_size;
    cudaFuncSetAttribute(router_kernel, cudaFuncAttributeMaxDynamicSharedMemorySize,
                         DSM_BYTES);
    router_kernel<<<NCTA, 256, DSM_BYTES>>>(x, W, out);
}

// round 10
// speedup vs baseline: 1.6712x; 1.1587x over previous
#include <cuda_runtime.h>
#include <cstdint>

// Problem constants
#define DDIM 4096
#define NEXP 64
#define NTOK 16384          // B*S
#define BM   128
#define KC   32             // K per stage
#define NSTAGE (DDIM / KC)  // 128
#define NCTA (NTOK / BM)    // 128
#define S36  36             // smem row stride (36 mod 32 = 4 -> conflict-free frags)

// Output layout (tuple flattened to float32 in reference order)
#define IDX_OFF   0
#define SC_OFF    32768
#define PB_OFF    65536
#define Z_OFF     1114112
#define IMP_OFF   1114113
#define LOAD_OFF  1114177

// Dynamic smem (float offsets): xh[2]@0/4608, xl[2]@9216/13824,
// wh[2]@18432/20736, wl[2]@23040/25344. Total 27648 floats = 108KB.
// After mainloop: ls[128][65] @0, st[129] @8320 (reuse).
#define XH(b) ((b) * 4608)
#define XL(b) (9216 + (b) * 4608)
#define WH(b) (18432 + (b) * 2304)
#define WL(b) (23040 + (b) * 2304)
#define DSM_BYTES (27648 * 4)

// Per-CTA partial stats: [0..63] importance, [64..127] counts, [128] z^2
__device__ float g_part[NCTA][129];
__device__ unsigned int g_ctr = 0;   // self-resetting via atomicInc wrap

// ---------- helpers ----------
__device__ __forceinline__ void tf32pair(float v, uint32_t& h, uint32_t& l) {
    asm("cvt.rna.tf32.f32 %0, %1;" : "=r"(h) : "f"(v));
    float r = v - __uint_as_float(h);
    asm("cvt.rna.tf32.f32 %0, %1;" : "=r"(l) : "f"(r));
}
__device__ __forceinline__ void mma8(float* d,
                                     uint32_t a0, uint32_t a1, uint32_t a2, uint32_t a3,
                                     uint32_t b0, uint32_t b1) {
    asm volatile(
        "mma.sync.aligned.m16n8k8.row.col.f32.tf32.tf32.f32 "
        "{%0,%1,%2,%3},{%4,%5,%6,%7},{%8,%9},{%0,%1,%2,%3};"
        : "+f"(d[0]), "+f"(d[1]), "+f"(d[2]), "+f"(d[3])
        : "r"(a0), "r"(a1), "r"(a2), "r"(a3), "r"(b0), "r"(b1));
}

// ---------- single fused kernel ----------
// grid = 128 CTAs (one per 128-token tile), block = 512 threads (16 warps,
// 4/SMSP). Warp tile: 16 rows x 32 experts (nt=4), 3-product tf32 emulation
// (hh + hl + lh; ll term ~2^-22 relative, below fp32 accumulation noise).
extern "C" __global__ void __launch_bounds__(512, 1)
router_kernel(const float* __restrict__ x, const float* __restrict__ W,
              float* __restrict__ out) {
    extern __shared__ __align__(16) float dsm[];

    const int tid  = threadIdx.x;
    const int warp = tid >> 5;
    const int lane = tid & 31;
    const int g = lane >> 2;      // group row
    const int t = lane & 3;       // thread-in-group
    const int rowbase = blockIdx.x * BM;
    const float* xg0 = x + (size_t)rowbase * DDIM;

    const int wrow  = (warp >> 1) * 16;   // 8 row blocks
    const int cbase = (warp & 1) * 32;    // 2 expert halves

    // ---- register-prefetch double-buffered loader ----
    // x: 1024 quads/stage -> 2 per thread; w: 512 quads -> 1 per thread.
    float4 xr[2], wr;
    #pragma unroll
    for (int i = 0; i < 2; i++) {
        int c = tid + 512 * i, r = c >> 3, q = c & 7;
        xr[i] = *(const float4*)(xg0 + (size_t)r * DDIM + (q << 2));
    }
    {
        int r = tid >> 3, q = tid & 7;
        wr = *(const float4*)(W + (size_t)r * DDIM + (q << 2));
    }

    float acc[4][4];
    #pragma unroll
    for (int nt = 0; nt < 4; nt++)
        #pragma unroll
        for (int e = 0; e < 4; e++) acc[nt][e] = 0.0f;

    #pragma unroll 1
    for (int s = 0; s < NSTAGE; s++) {
        const int b = s & 1;

        // prefetch next stage
        float4 xn[2], wn;
        if (s + 1 < NSTAGE) {
            const float* xg = xg0 + (s + 1) * KC;
            const float* wg = W + (s + 1) * KC;
            #pragma unroll
            for (int i = 0; i < 2; i++) {
                int c = tid + 512 * i, r = c >> 3, q = c & 7;
                xn[i] = *(const float4*)(xg + (size_t)r * DDIM + (q << 2));
            }
            {
                int r = tid >> 3, q = tid & 7;
                wn = *(const float4*)(wg + (size_t)r * DDIM + (q << 2));
            }
        }

        // convert current stage fp32 -> (tf32 hi, tf32 lo), store to smem.
        // NOTE: stores to buffer b are ordered against stage s-1's MMA reads of
        // buffer b^1 trivially (different buffer) and against stage s-2's reads
        // of buffer b by the single sync in stage s-1. One sync/stage suffices.
        #pragma unroll
        for (int i = 0; i < 2; i++) {
            int c = tid + 512 * i, r = c >> 3, q = c & 7;
            uint4 h, l;
            tf32pair(xr[i].x, h.x, l.x);
            tf32pair(xr[i].y, h.y, l.y);
            tf32pair(xr[i].z, h.z, l.z);
            tf32pair(xr[i].w, h.w, l.w);
            int off = r * S36 + (q << 2);
            *(uint4*)(dsm + XH(b) + off) = h;
            *(uint4*)(dsm + XL(b) + off) = l;
        }
        {
            int r = tid >> 3, q = tid & 7;
            uint4 h, l;
            tf32pair(wr.x, h.x, l.x);
            tf32pair(wr.y, h.y, l.y);
            tf32pair(wr.z, h.z, l.z);
            tf32pair(wr.w, h.w, l.w);
            int off = r * S36 + (q << 2);
            *(uint4*)(dsm + WH(b) + off) = h;
            *(uint4*)(dsm + WL(b) + off) = l;
        }
        __syncthreads();

        // ---- MMA phase: 4 k8-steps, 4 n-tiles, 3 products each ----
        const uint32_t* xh = (const uint32_t*)(dsm + XH(b)) + (wrow + g) * S36 + t;
        const uint32_t* xl = (const uint32_t*)(dsm + XL(b)) + (wrow + g) * S36 + t;
        const uint32_t* wh = (const uint32_t*)(dsm + WH(b)) + (cbase + g) * S36 + t;
        const uint32_t* wl = (const uint32_t*)(dsm + WL(b)) + (cbase + g) * S36 + t;

        #pragma unroll
        for (int kq = 0; kq < 4; kq++) {
            const int k0 = kq * 8;
            // A frags: a0:(g,t) a1:(g+8,t) a2:(g,t+4) a3:(g+8,t+4)
            uint32_t ah0 = xh[k0],     ah1 = xh[8 * S36 + k0];
            uint32_t ah2 = xh[k0 + 4], ah3 = xh[8 * S36 + k0 + 4];
            uint32_t al0 = xl[k0],     al1 = xl[8 * S36 + k0];
            uint32_t al2 = xl[k0 + 4], al3 = xl[8 * S36 + k0 + 4];
            #pragma unroll
            for (int nt = 0; nt < 4; nt++) {
                // B frags: expert = cbase + nt*8 + g
                const uint32_t* wph = wh + nt * 8 * S36;
                const uint32_t* wpl = wl + nt * 8 * S36;
                uint32_t bh0 = wph[k0], bh1 = wph[k0 + 4];
                uint32_t bl0 = wpl[k0], bl1 = wpl[k0 + 4];
                mma8(acc[nt], al0, al1, al2, al3, bh0, bh1);  // lh
                mma8(acc[nt], ah0, ah1, ah2, ah3, bl0, bl1);  // hl
                mma8(acc[nt], ah0, ah1, ah2, ah3, bh0, bh1);  // hh
            }
        }

        #pragma unroll
        for (int i = 0; i < 2; i++) xr[i] = xn[i];
        wr = wn;
    }
    __syncthreads();   // last stage's MMAs done before smem reuse

    // ---- epilogue: logits -> smem ls[128][65] ----
    // C frags: c0:(g,2t) c1:(g,2t+1) c2:(g+8,2t) c3:(g+8,2t+1)
    float* ls = dsm;
    float* st = dsm + 8320;
    #pragma unroll
    for (int nt = 0; nt < 4; nt++) {
        const int c0 = cbase + nt * 8 + 2 * t;
        ls[(wrow + g) * 65 + c0]         = acc[nt][0];
        ls[(wrow + g) * 65 + c0 + 1]     = acc[nt][1];
        ls[(wrow + g + 8) * 65 + c0]     = acc[nt][2];
        ls[(wrow + g + 8) * 65 + c0 + 1] = acc[nt][3];
    }
    if (tid < 129) st[tid] = 0.0f;
    __syncthreads();

    // ---- router: 16 warps, 8 rows per warp ----
    const float NEG_INF = __int_as_float(0xff800000u);
    float imp0 = 0.f, imp1 = 0.f, cnt0 = 0.f, cnt1 = 0.f, z2 = 0.f;
    float* probs_out = out + PB_OFF;

    #pragma unroll 2
    for (int it = 0; it < 8; it++) {
        const int rl = warp * 8 + it;
        const int row = rowbase + rl;
        const float va = ls[rl * 65 + lane];
        const float vb = ls[rl * 65 + lane + 32];

        float bv; int bi;
        if (va >= vb) { bv = va; bi = lane; } else { bv = vb; bi = lane + 32; }
        #pragma unroll
        for (int off = 16; off; off >>= 1) {
            float ov = __shfl_xor_sync(0xffffffffu, bv, off);
            int   oi = __shfl_xor_sync(0xffffffffu, bi, off);
            if (ov > bv || (ov == bv && oi < bi)) { bv = ov; bi = oi; }
        }
        float va2 = (lane == bi)      ? NEG_INF : va;
        float vb2 = (lane + 32 == bi) ? NEG_INF : vb;
        float sv; int si;
        if (va2 >= vb2) { sv = va2; si = lane; } else { sv = vb2; si = lane + 32; }
        #pragma unroll
        for (int off = 16; off; off >>= 1) {
            float ov = __shfl_xor_sync(0xffffffffu, sv, off);
            int   oi = __shfl_xor_sync(0xffffffffu, si, off);
            if (ov > sv || (ov == sv && oi < si)) { sv = ov; si = oi; }
        }

        const float ea = __expf(va - bv);
        const float eb = __expf(vb - bv);
        float ssum = ea + eb;
        #pragma unroll
        for (int off = 16; off; off >>= 1)
            ssum += __shfl_xor_sync(0xffffffffu, ssum, off);
        const float inv = 1.0f / ssum;
        const float pa = ea * inv, pb = eb * inv;

        probs_out[(size_t)row * 64 + lane]      = pa;
        probs_out[(size_t)row * 64 + lane + 32] = pb;

        imp0 += pa; imp1 += pb;
        cnt0 += (bi == lane      ? 1.f : 0.f) + (si == lane      ? 1.f : 0.f);
        cnt1 += (bi == lane + 32 ? 1.f : 0.f) + (si == lane + 32 ? 1.f : 0.f);

        if (lane == 0) {
            const float z = bv + __logf(ssum);
            z2 += z * z;
            out[IDX_OFF + row * 2]     = (float)bi;
            out[IDX_OFF + row * 2 + 1] = (float)si;
            const float e2 = __expf(sv - bv);
            const float dn = 1.0f / (1.0f + e2);
            out[SC_OFF + row * 2]     = dn;
            out[SC_OFF + row * 2 + 1] = e2 * dn;
        }
    }

    // ---- CTA-level stats reduce in smem, then one row of g_part ----
    atomicAdd(&st[lane],      imp0);
    atomicAdd(&st[lane + 32], imp1);
    atomicAdd(&st[64 + lane], cnt0);
    atomicAdd(&st[96 + lane], cnt1);
    if (lane == 0) atomicAdd(&st[128], z2);
    __syncthreads();

    if (tid < 129) g_part[blockIdx.x][tid] = st[tid];

    // ---- last-CTA finalize (self-resetting counter) ----
    __shared__ unsigned int s_last;
    __threadfence();
    __syncthreads();
    if (tid == 0) {
        unsigned int old = atomicInc(&g_ctr, NCTA - 1);
        s_last = (old == NCTA - 1) ? 1u : 0u;
    }
    __syncthreads();
    if (s_last && tid < 129) {
        __threadfence();
        float ssum = 0.f;
        #pragma unroll 1
        for (int c = 0; c < NCTA; c++) ssum += g_part[c][tid];
        if (tid < 64)       out[IMP_OFF + tid]         = ssum * (1.0f / 16384.0f);
        else if (tid < 128) out[LOAD_OFF + (tid - 64)] = ssum * (1.0f / 32768.0f);
        else                out[Z_OFF]                 = ssum * (1.0f / 16384.0f);
    }
}

extern "C" void kernel_launch(void* const* d_in, const int* in_sizes, int n_in,
                              void* d_out, int out_size) {
    const float* x = (const float*)d_in[0];   // [4,4096,4096] f32
    const float* W = (const float*)d_in[1];   // [64,4096] f32
    float* out = (float*)d_out;
    (void)in_sizes; (void)n_in; (void)out_size;
    cudaFuncSetAttribute(router_kernel, cudaFuncAttributeMaxDynamicSharedMemorySize,
                         DSM_BYTES);
    router_kernel<<<NCTA, 512, DSM_BYTES>>>(x, W, out);
}

// round 11
// speedup vs baseline: 1.8309x; 1.0955x over previous
#include <cuda_runtime.h>
#include <cstdint>

// Problem constants
#define DDIM 4096
#define NEXP 64
#define NTOK 16384          // B*S
#define BM   128
#define KC   32             // K per stage
#define NSTAGE (DDIM / KC)  // 128
#define NCTA (NTOK / BM)    // 128
#define S36  36             // smem row stride (36 mod 32 = 4 -> conflict-free frags)

// Output layout (tuple flattened to float32 in reference order)
#define IDX_OFF   0
#define SC_OFF    32768
#define PB_OFF    65536
#define Z_OFF     1114112
#define IMP_OFF   1114113
#define LOAD_OFF  1114177

// Dynamic smem (float offsets): xh[2]@0/4608, xl[2]@9216/13824,
// wh[2]@18432/20736, wl[2]@23040/25344. Total 27648 floats = 108KB.
// After mainloop: ls[128][65] @0, st[129] @8320 (reuse).
#define XH(b) ((b) * 4608)
#define XL(b) (9216 + (b) * 4608)
#define WH(b) (18432 + (b) * 2304)
#define WL(b) (23040 + (b) * 2304)
#define DSM_BYTES (27648 * 4)

// Per-CTA partial stats: [0..63] importance, [64..127] counts, [128] z^2
__device__ float g_part[NCTA][129];
__device__ unsigned int g_ctr = 0;   // self-resetting via atomicInc wrap

// ---------- helpers ----------
__device__ __forceinline__ void tf32pair(float v, uint32_t& h, uint32_t& l) {
    asm("cvt.rna.tf32.f32 %0, %1;" : "=r"(h) : "f"(v));
    float r = v - __uint_as_float(h);
    asm("cvt.rna.tf32.f32 %0, %1;" : "=r"(l) : "f"(r));
}
__device__ __forceinline__ void mma8(float* d,
                                     uint32_t a0, uint32_t a1, uint32_t a2, uint32_t a3,
                                     uint32_t b0, uint32_t b1) {
    asm volatile(
        "mma.sync.aligned.m16n8k8.row.col.f32.tf32.tf32.f32 "
        "{%0,%1,%2,%3},{%4,%5,%6,%7},{%8,%9},{%0,%1,%2,%3};"
        : "+f"(d[0]), "+f"(d[1]), "+f"(d[2]), "+f"(d[3])
        : "r"(a0), "r"(a1), "r"(a2), "r"(a3), "r"(b0), "r"(b1));
}
// ldmatrix x4: loads full m16k8 tf32 A fragment (a0..a3) in one instruction.
__device__ __forceinline__ void ldsm4(uint32_t& r0, uint32_t& r1,
                                      uint32_t& r2, uint32_t& r3, uint32_t addr) {
    asm volatile("ldmatrix.sync.aligned.m8n8.x4.shared.b16 {%0,%1,%2,%3}, [%4];"
                 : "=r"(r0), "=r"(r1), "=r"(r2), "=r"(r3) : "r"(addr));
}

// ---------- single fused kernel ----------
// grid = 128 CTAs, block = 256 threads (8 warps, 2/SMSP).
// Warp tile: 32 rows x 32 experts (8 acc tiles = 8 independent MMA chains).
// A frags via ldmatrix.x4; 3-product tf32 emulation (hh + hl + lh).
extern "C" __global__ void __launch_bounds__(256, 1)
router_kernel(const float* __restrict__ x, const float* __restrict__ W,
              float* __restrict__ out) {
    extern __shared__ __align__(16) float dsm[];

    const int tid  = threadIdx.x;
    const int warp = tid >> 5;
    const int lane = tid & 31;
    const int g = lane >> 2;      // group row
    const int t = lane & 3;       // thread-in-group
    const int rowbase = blockIdx.x * BM;
    const float* xg0 = x + (size_t)rowbase * DDIM;

    const int wrow  = (warp >> 1) * 32;   // 4 row blocks of 32
    const int cbase = (warp & 1) * 32;    // 2 expert halves

    uint32_t dsm_a;
    asm("{ .reg .u64 t0; cvta.to.shared.u64 t0, %1; cvt.u32.u64 %0, t0; }"
        : "=r"(dsm_a) : "l"(dsm));

    // ldmatrix lane address (element offset within a tile buffer):
    // tiles: 0:(rows 0-7,k0-3) 1:(rows 8-15,k0-3) 2:(rows 0-7,k4-7) 3:(rows 8-15,k4-7)
    const int arow = wrow + (lane & 7) + ((lane >> 3) & 1) * 8;
    const int aoff = arow * S36 + ((lane >> 4) & 1) * 4;

    // ---- register-prefetch double-buffered loader (R9 scheme) ----
    float4 xr[4], wr[2];
    #pragma unroll
    for (int i = 0; i < 4; i++) {
        int c = tid + 256 * i, r = c >> 3, q = c & 7;
        xr[i] = *(const float4*)(xg0 + (size_t)r * DDIM + (q << 2));
    }
    #pragma unroll
    for (int i = 0; i < 2; i++) {
        int c = tid + 256 * i, r = c >> 3, q = c & 7;
        wr[i] = *(const float4*)(W + (size_t)r * DDIM + (q << 2));
    }

    float acc[2][4][4];   // [row block][n tile][frag]
    #pragma unroll
    for (int rb = 0; rb < 2; rb++)
        #pragma unroll
        for (int nt = 0; nt < 4; nt++)
            #pragma unroll
            for (int e = 0; e < 4; e++) acc[rb][nt][e] = 0.0f;

    #pragma unroll 1
    for (int s = 0; s < NSTAGE; s++) {
        const int b = s & 1;

        // prefetch next stage
        float4 xn[4], wn[2];
        if (s + 1 < NSTAGE) {
            const float* xg = xg0 + (s + 1) * KC;
            const float* wg = W + (s + 1) * KC;
            #pragma unroll
            for (int i = 0; i < 4; i++) {
                int c = tid + 256 * i, r = c >> 3, q = c & 7;
                xn[i] = *(const float4*)(xg + (size_t)r * DDIM + (q << 2));
            }
            #pragma unroll
            for (int i = 0; i < 2; i++) {
                int c = tid + 256 * i, r = c >> 3, q = c & 7;
                wn[i] = *(const float4*)(wg + (size_t)r * DDIM + (q << 2));
            }
        }

        // convert current stage fp32 -> (tf32 hi, tf32 lo), store to smem
        #pragma unroll
        for (int i = 0; i < 4; i++) {
            int c = tid + 256 * i, r = c >> 3, q = c & 7;
            uint4 h, l;
            tf32pair(xr[i].x, h.x, l.x);
            tf32pair(xr[i].y, h.y, l.y);
            tf32pair(xr[i].z, h.z, l.z);
            tf32pair(xr[i].w, h.w, l.w);
            int off = r * S36 + (q << 2);
            *(uint4*)(dsm + XH(b) + off) = h;
            *(uint4*)(dsm + XL(b) + off) = l;
        }
        #pragma unroll
        for (int i = 0; i < 2; i++) {
            int c = tid + 256 * i, r = c >> 3, q = c & 7;
            uint4 h, l;
            tf32pair(wr[i].x, h.x, l.x);
            tf32pair(wr[i].y, h.y, l.y);
            tf32pair(wr[i].z, h.z, l.z);
            tf32pair(wr[i].w, h.w, l.w);
            int off = r * S36 + (q << 2);
            *(uint4*)(dsm + WH(b) + off) = h;
            *(uint4*)(dsm + WL(b) + off) = l;
        }
        __syncthreads();

        // ---- MMA phase: 4 k8-steps, 2 row blocks, 4 n-tiles, 3 products ----
        const uint32_t ah_base = dsm_a + (uint32_t)(XH(b) + aoff) * 4;
        const uint32_t al_base = dsm_a + (uint32_t)(XL(b) + aoff) * 4;
        const uint32_t* wh = (const uint32_t*)(dsm + WH(b)) + (cbase + g) * S36 + t;
        const uint32_t* wl = (const uint32_t*)(dsm + WL(b)) + (cbase + g) * S36 + t;

        #pragma unroll
        for (int kq = 0; kq < 4; kq++) {
            const int k0 = kq * 8;
            uint32_t ah[2][4], al[2][4];
            #pragma unroll
            for (int rb = 0; rb < 2; rb++) {
                ldsm4(ah[rb][0], ah[rb][1], ah[rb][2], ah[rb][3],
                      ah_base + (uint32_t)(rb * 16 * S36 + k0) * 4);
                ldsm4(al[rb][0], al[rb][1], al[rb][2], al[rb][3],
                      al_base + (uint32_t)(rb * 16 * S36 + k0) * 4);
            }
            #pragma unroll
            for (int nt = 0; nt < 4; nt++) {
                const uint32_t* wph = wh + nt * 8 * S36;
                const uint32_t* wpl = wl + nt * 8 * S36;
                uint32_t bh0 = wph[k0], bh1 = wph[k0 + 4];
                uint32_t bl0 = wpl[k0], bl1 = wpl[k0 + 4];
                #pragma unroll
                for (int rb = 0; rb < 2; rb++) {
                    mma8(acc[rb][nt], al[rb][0], al[rb][1], al[rb][2], al[rb][3],
                         bh0, bh1);                                           // lh
                    mma8(acc[rb][nt], ah[rb][0], ah[rb][1], ah[rb][2], ah[rb][3],
                         bl0, bl1);                                           // hl
                    mma8(acc[rb][nt], ah[rb][0], ah[rb][1], ah[rb][2], ah[rb][3],
                         bh0, bh1);                                           // hh
                }
            }
        }

        #pragma unroll
        for (int i = 0; i < 4; i++) xr[i] = xn[i];
        #pragma unroll
        for (int i = 0; i < 2; i++) wr[i] = wn[i];
    }
    __syncthreads();   // last stage's MMAs done before smem reuse

    // ---- epilogue: logits -> smem ls[128][65] ----
    float* ls = dsm;
    float* st = dsm + 8320;
    #pragma unroll
    for (int rb = 0; rb < 2; rb++)
        #pragma unroll
        for (int nt = 0; nt < 4; nt++) {
            const int c0 = cbase + nt * 8 + 2 * t;
            const int r0 = wrow + rb * 16 + g;
            ls[r0 * 65 + c0]           = acc[rb][nt][0];
            ls[r0 * 65 + c0 + 1]       = acc[rb][nt][1];
            ls[(r0 + 8) * 65 + c0]     = acc[rb][nt][2];
            ls[(r0 + 8) * 65 + c0 + 1] = acc[rb][nt][3];
        }
    if (tid < 129) st[tid] = 0.0f;
    __syncthreads();

    // ---- router: 8 warps, 16 rows per warp (proven code) ----
    const float NEG_INF = __int_as_float(0xff800000u);
    float imp0 = 0.f, imp1 = 0.f, cnt0 = 0.f, cnt1 = 0.f, z2 = 0.f;
    float* probs_out = out + PB_OFF;

    #pragma unroll 2
    for (int it = 0; it < 16; it++) {
        const int rl = warp * 16 + it;
        const int row = rowbase + rl;
        const float va = ls[rl * 65 + lane];
        const float vb = ls[rl * 65 + lane + 32];

        float bv; int bi;
        if (va >= vb) { bv = va; bi = lane; } else { bv = vb; bi = lane + 32; }
        #pragma unroll
        for (int off = 16; off; off >>= 1) {
            float ov = __shfl_xor_sync(0xffffffffu, bv, off);
            int   oi = __shfl_xor_sync(0xffffffffu, bi, off);
            if (ov > bv || (ov == bv && oi < bi)) { bv = ov; bi = oi; }
        }
        float va2 = (lane == bi)      ? NEG_INF : va;
        float vb2 = (lane + 32 == bi) ? NEG_INF : vb;
        float sv; int si;
        if (va2 >= vb2) { sv = va2; si = lane; } else { sv = vb2; si = lane + 32; }
        #pragma unroll
        for (int off = 16; off; off >>= 1) {
            float ov = __shfl_xor_sync(0xffffffffu, sv, off);
            int   oi = __shfl_xor_sync(0xffffffffu, si, off);
            if (ov > sv || (ov == sv && oi < si)) { sv = ov; si = oi; }
        }

        const float ea = __expf(va - bv);
        const float eb = __expf(vb - bv);
        float ssum = ea + eb;
        #pragma unroll
        for (int off = 16; off; off >>= 1)
            ssum += __shfl_xor_sync(0xffffffffu, ssum, off);
        const float inv = 1.0f / ssum;
        const float pa = ea * inv, pb = eb * inv;

        probs_out[(size_t)row * 64 + lane]      = pa;
        probs_out[(size_t)row * 64 + lane + 32] = pb;

        imp0 += pa; imp1 += pb;
        cnt0 += (bi == lane      ? 1.f : 0.f) + (si == lane      ? 1.f : 0.f);
        cnt1 += (bi == lane + 32 ? 1.f : 0.f) + (si == lane + 32 ? 1.f : 0.f);

        if (lane == 0) {
            const float z = bv + __logf(ssum);
            z2 += z * z;
            out[IDX_OFF + row * 2]     = (float)bi;
            out[IDX_OFF + row * 2 + 1] = (float)si;
            const float e2 = __expf(sv - bv);
            const float dn = 1.0f / (1.0f + e2);
            out[SC_OFF + row * 2]     = dn;
            out[SC_OFF + row * 2 + 1] = e2 * dn;
        }
    }

    // ---- CTA-level stats reduce in smem, then one row of g_part ----
    atomicAdd(&st[lane],      imp0);
    atomicAdd(&st[lane + 32], imp1);
    atomicAdd(&st[64 + lane], cnt0);
    atomicAdd(&st[96 + lane], cnt1);
    if (lane == 0) atomicAdd(&st[128], z2);
    __syncthreads();

    if (tid < 129) g_part[blockIdx.x][tid] = st[tid];

    // ---- last-CTA finalize (self-resetting counter) ----
    __shared__ unsigned int s_last;
    __threadfence();
    __syncthreads();
    if (tid == 0) {
        unsigned int old = atomicInc(&g_ctr, NCTA - 1);
        s_last = (old == NCTA - 1) ? 1u : 0u;
    }
    __syncthreads();
    if (s_last && tid < 129) {
        __threadfence();
        float ssum = 0.f;
        #pragma unroll 1
        for (int c = 0; c < NCTA; c++) ssum += g_part[c][tid];
        if (tid < 64)       out[IMP_OFF + tid]         = ssum * (1.0f / 16384.0f);
        else if (tid < 128) out[LOAD_OFF + (tid - 64)] = ssum * (1.0f / 32768.0f);
        else                out[Z_OFF]                 = ssum * (1.0f / 16384.0f);
    }
}

extern "C" void kernel_launch(void* const* d_in, const int* in_sizes, int n_in,
                              void* d_out, int out_size) {
    const float* x = (const float*)d_in[0];   // [4,4096,4096] f32
    const float* W = (const float*)d_in[1];   // [64,4096] f32
    float* out = (float*)d_out;
    (void)in_sizes; (void)n_in; (void)out_size;
    cudaFuncSetAttribute(router_kernel, cudaFuncAttributeMaxDynamicSharedMemorySize,
                         DSM_BYTES);
    router_kernel<<<NCTA, 256, DSM_BYTES>>>(x, W, out);
}